// round 4
// baseline (speedup 1.0000x reference)
#include <cuda_runtime.h>
#include <math_constants.h>

// B=8, U=V=13 (UV=169), H=128, W=160 (HW=20480), TRUNC=4, disp -6..6
#define UV 169
#define VD 13
#define HW 20480
#define PIX 16                  // pixels per CTA
#define NT 64                   // 4 threads cooperate per pixel
#define RSTRIDE 21              // v-slot for v in [-4,16]
#define NROWS 14                // u rows 0..12 + all-pad row 13
#define SLAB 295                // 14*21=294, +1 so stride is odd (bank spread 7)
#define SMEM_FLOATS (PIX * SLAB)   // 4720 floats = 18880 B -> 12 CTAs/SM
#define NEGBIG (-1e30f)

__global__ __launch_bounds__(NT, 12)
void flow_regression_kernel(const float* __restrict__ x, float* __restrict__ out) {
    __shared__ float s[SMEM_FLOATS];   // s[pix][SLAB]

    const int tid   = threadIdx.x;
    const int blk   = blockIdx.x;            // 0 .. 8*1280-1
    const int b     = blk / (HW / PIX);
    const int chunk = blk % (HW / PIX);

    const float* xb = x + b * (UV * HW) + chunk * PIX;

    // ---- Phase 1a: load 169 planes x 16 floats (676 float4 jobs), transposed ----
    // job i: plane = i>>2 (gmem plane index = u*13+vl directly), o = i&3
    #pragma unroll 4
    for (int i = tid; i < UV * (PIX / 4); i += NT) {
        int plane = i >> 2;
        int o     = i & 3;
        float4 v = *(const float4*)(xb + plane * HW + o * 4);
        int u  = (plane * 5) >> 6;           // plane/13 for plane<832: u = plane*5/64? no
        u = plane / 13;                       // compiler lowers to mul-hi
        int vl = plane - u * VD;
        float* d = s + (o * 4) * SLAB + u * RSTRIDE + vl + 4;
        d[0 * SLAB] = v.x;
        d[1 * SLAB] = v.y;
        d[2 * SLAB] = v.z;
        d[3 * SLAB] = v.w;
    }

    // ---- Phase 1b: fill ONLY pad slots with -1e30 (disjoint from data; no sync needed) ----
    // pad slots (125): [0..3], {21u+17..21u+24 : u=0..11}, [269..293]
    #pragma unroll 4
    for (int i = tid; i < 125 * PIX; i += NT) {
        int pix  = i & (PIX - 1);
        int slot = i >> 4;
        int off;
        if (slot < 4)        off = slot;
        else if (slot < 100) { int t = slot - 4; off = 21 * (t >> 3) + 17 + (t & 7); }
        else                 off = 269 + (slot - 100);
        s[pix * SLAB + off] = NEGBIG;
    }
    __syncthreads();

    const int sub = tid & 3;        // quarter of per-pixel work
    const int p   = tid >> 2;       // pixel 0..15
    const float* sp = s + p * SLAB;

    // ---- Pass A: argmax over 169 (ascending uv order per lane; ties -> lowest uv) ----
    float m  = -CUDART_INF_F;
    int   am = 0;
    {
        const float* r = sp + 4 + sub;   // v slot for v=sub
        #pragma unroll
        for (int u = 0; u < VD; u++) {
            #pragma unroll
            for (int j = 0; j < 3; j++) {           // v = sub, sub+4, sub+8 (<=11)
                float v = r[j * 4];
                int idx = u * VD + sub + j * 4;
                if (v > m) { m = v; am = idx; }
            }
            if (sub == 0) {                          // v = 12 handled by sub 0
                float v = r[12];
                int idx = u * VD + 12;
                if (v > m) { m = v; am = idx; }
            }
            r += RSTRIDE;
        }
    }
    // combine across the 4 lanes of this pixel (first-occurrence tie-break)
    #pragma unroll
    for (int off = 1; off <= 2; off <<= 1) {
        float mo = __shfl_xor_sync(0xffffffffu, m,  off);
        int   ao = __shfl_xor_sync(0xffffffffu, am, off);
        if (mo > m || (mo == m && ao < am)) { m = mo; am = ao; }
    }
    const int ui = am / VD;
    const int vi = am - ui * VD;

    // ---- Pass B: 9x9 window softmax, no bounds checks (pads are -1e30 -> e=0) ----
    float Z = 0.0f, sU = 0.0f, sV = 0.0f;
    {
        const float* bp = sp + vi + sub;
        const float wu0 = (float)(ui - 10);          // u-6 = ui + du - 10
        const float wv0 = (float)(vi + sub - 10);    // v-6 = vi + dv - 10
        #pragma unroll
        for (int du = 0; du < 9; du++) {
            int u = ui + du - 4;
            int row = ((unsigned)u <= 12u) ? u : 13; // out-of-range -> pad row
            const float* r = bp + row * RSTRIDE;
            float wu = wu0 + (float)du;
            #pragma unroll
            for (int j = 0; j < 2; j++) {            // dv = sub, sub+4 (<= 7)
                float e = __expf(r[j * 4] - m);
                Z  += e;
                sU += e * wu;
                sV += e * (wv0 + (float)(j * 4));
            }
            if (sub == 0) {                          // dv = 8 handled by sub 0
                float e = __expf(r[8] - m);
                Z  += e;
                sU += e * wu;
                sV += e * (wv0 + 8.0f);
            }
        }
    }
    #pragma unroll
    for (int off = 1; off <= 2; off <<= 1) {
        Z  += __shfl_xor_sync(0xffffffffu, Z,  off);
        sU += __shfl_xor_sync(0xffffffffu, sU, off);
        sV += __shfl_xor_sync(0xffffffffu, sV, off);
    }

    if (sub == 0) {
        const float inv = __frcp_rn(Z);
        const int pix = chunk * PIX + p;
        out[(b * 2 + 0) * HW + pix] = sU * inv;
        out[(b * 2 + 1) * HW + pix] = sV * inv;
    }
}

extern "C" void kernel_launch(void* const* d_in, const int* in_sizes, int n_in,
                              void* d_out, int out_size) {
    (void)in_sizes; (void)n_in; (void)out_size;
    const float* x = (const float*)d_in[0];
    float* out = (float*)d_out;

    // Ask for max shared-memory carveout so 12 CTAs/SM actually fit.
    cudaFuncSetAttribute(flow_regression_kernel,
                         cudaFuncAttributePreferredSharedMemoryCarveout, 100);

    const int nblocks = 8 * (HW / PIX);   // 10240
    flow_regression_kernel<<<nblocks, NT>>>(x, out);
}

// round 6
// speedup vs baseline: 1.1315x; 1.1315x over previous
#include <cuda_runtime.h>
#include <math_constants.h>
#include <cstdint>

// B=8, U=V=13 (UV=169), H=128, W=160 (HW=20480), TRUNC=4, disp -6..6
#define UV 169
#define VD 13
#define HW 20480
#define PIX 32                   // pixels per chunk
#define NT 128                   // 4 threads cooperate per pixel in compute
#define RSTRIDE 21               // v-slot for v in [-4,16]
#define SLAB 295                 // 14*21=294, +1 -> odd stride (lane*295 mod 32 = lane*7: conflict-free)
#define BUF (PIX * SLAB)         // 9440 floats per buffer
#define SMEM_BYTES (2 * BUF * 4) // 75520 B -> 3 CTAs/SM
#define CH 8                     // chunks per CTA
#define CHUNKS_PER_B (HW / PIX)  // 640
#define NBLOCKS (8 * CHUNKS_PER_B / CH)  // 640
#define NEGBIG (-1e30f)

__device__ __forceinline__ void cp_async4(unsigned int dst, const float* src) {
    asm volatile("cp.async.ca.shared.global [%0], [%1], 4;" :: "r"(dst), "l"(src) : "memory");
}
__device__ __forceinline__ void cp_commit() {
    asm volatile("cp.async.commit_group;" ::: "memory");
}
template<int N>
__device__ __forceinline__ void cp_wait() {
    asm volatile("cp.async.wait_group %0;" :: "n"(N) : "memory");
}

__global__ __launch_bounds__(NT)
void flow_regression_kernel(const float* __restrict__ x, float* __restrict__ out) {
    extern __shared__ float s[];      // 2 x s[pix][SLAB]
    const int tid  = threadIdx.x;
    const int lane = tid & 31;
    const int wid  = tid >> 5;
    const int bid  = blockIdx.x;

    // ---- Fill pad slots of BOTH buffers once (loads never touch pad slots) ----
    // pad slots per pixel (125): [0..3], {21u+17 .. 21u+24 : u=0..11}, [269..293]
    #pragma unroll 4
    for (int i = tid; i < 125 * PIX; i += NT) {
        int pix  = i & (PIX - 1);
        int slot = i >> 5;
        int off;
        if (slot < 4)        off = slot;
        else if (slot < 100) { int t = slot - 4; off = 21 * (t >> 3) + 17 + (t & 7); }
        else                 off = 269 + (slot - 100);
        s[pix * SLAB + off]       = NEGBIG;
        s[BUF + pix * SLAB + off] = NEGBIG;
    }

    const unsigned int sbase = (unsigned int)__cvta_generic_to_shared(s);
    const int base_chunk = bid * CH;

    const int sub = tid & 3;          // quarter of per-pixel work
    const int p   = tid >> 2;         // pixel 0..31

    // ---- issue loads for one chunk into buffer nb ----
    // warp 'wid' covers planes wid, wid+4, ... ; one cp.async per plane:
    // 32 lanes move a contiguous 128B gmem line into lane-scattered smem (no conflicts).
    auto issue_load = [&](int g, int nb) {
        int b  = g / CHUNKS_PER_B;
        int ch = g - b * CHUNKS_PER_B;
        const float* gp = x + (size_t)b * (UV * HW) + ch * PIX + wid * HW + lane;
        unsigned int dbase = sbase + (unsigned int)(nb * BUF + lane * SLAB + 4) * 4u;
        int u = 0, vl = wid;
        #pragma unroll 4
        for (int plane = wid; plane < UV; plane += 4) {
            cp_async4(dbase + (unsigned int)(u * RSTRIDE + vl) * 4u, gp);
            gp += 4 * HW;
            vl += 4;
            if (vl >= VD) { vl -= VD; u += 1; }
        }
        cp_commit();
    };

    issue_load(base_chunk, 0);        // prologue: chunk 0 -> buf 0

    for (int c = 0; c < CH; c++) {
        const int nb = c & 1;
        if (c + 1 < CH) { issue_load(base_chunk + c + 1, nb ^ 1); cp_wait<1>(); }
        else            { cp_wait<0>(); }
        __syncthreads();              // buffer nb fully loaded & visible (also covers pad fill)

        const float* sp = s + nb * BUF + p * SLAB;

        // ---- Pass A: argmax over 169 (ascending uv per lane; ties -> lowest uv) ----
        float m  = -CUDART_INF_F;
        int   am = 0;
        {
            const float* r = sp + 4 + sub;
            #pragma unroll
            for (int u = 0; u < VD; u++) {
                #pragma unroll
                for (int j = 0; j < 3; j++) {          // v = sub, sub+4, sub+8
                    float v = r[j * 4];
                    int idx = u * VD + sub + j * 4;
                    if (v > m) { m = v; am = idx; }
                }
                if (sub == 0) {                        // v = 12 handled by sub 0
                    float v = r[12];
                    int idx = u * VD + 12;
                    if (v > m) { m = v; am = idx; }
                }
                r += RSTRIDE;
            }
        }
        #pragma unroll
        for (int off = 1; off <= 2; off <<= 1) {
            float mo = __shfl_xor_sync(0xffffffffu, m,  off);
            int   ao = __shfl_xor_sync(0xffffffffu, am, off);
            if (mo > m || (mo == m && ao < am)) { m = mo; am = ao; }
        }
        const int ui = am / VD;
        const int vi = am - ui * VD;

        // ---- Pass B: 9x9 window softmax, no bounds checks (pads -> exp = 0) ----
        float Z = 0.0f, sU = 0.0f, sV = 0.0f;
        {
            const float* bp = sp + vi + sub;
            const float wu0 = (float)(ui - 10);        // u-6 = ui + du - 10
            const float wv0 = (float)(vi + sub - 10);  // v-6 = vi + dv - 10
            #pragma unroll
            for (int du = 0; du < 9; du++) {
                int u = ui + du - 4;
                int row = ((unsigned)u <= 12u) ? u : 13;
                const float* r = bp + row * RSTRIDE;
                float wu = wu0 + (float)du;
                #pragma unroll
                for (int j = 0; j < 2; j++) {          // dv = sub, sub+4
                    float e = __expf(r[j * 4] - m);
                    Z  += e;
                    sU += e * wu;
                    sV += e * (wv0 + (float)(j * 4));
                }
                if (sub == 0) {                        // dv = 8 handled by sub 0
                    float e = __expf(r[8] - m);
                    Z  += e;
                    sU += e * wu;
                    sV += e * (wv0 + 8.0f);
                }
            }
        }
        #pragma unroll
        for (int off = 1; off <= 2; off <<= 1) {
            Z  += __shfl_xor_sync(0xffffffffu, Z,  off);
            sU += __shfl_xor_sync(0xffffffffu, sU, off);
            sV += __shfl_xor_sync(0xffffffffu, sV, off);
        }

        if (sub == 0) {
            const int g  = base_chunk + c;
            const int b  = g / CHUNKS_PER_B;
            const int ch = g - b * CHUNKS_PER_B;
            const float inv = __frcp_rn(Z);
            const int pix = ch * PIX + p;
            out[(b * 2 + 0) * HW + pix] = sU * inv;
            out[(b * 2 + 1) * HW + pix] = sV * inv;
        }
        __syncthreads();              // all reads of buffer nb done before it is refilled
    }
}

extern "C" void kernel_launch(void* const* d_in, const int* in_sizes, int n_in,
                              void* d_out, int out_size) {
    (void)in_sizes; (void)n_in; (void)out_size;
    const float* x = (const float*)d_in[0];
    float* out = (float*)d_out;

    cudaFuncSetAttribute(flow_regression_kernel,
                         cudaFuncAttributeMaxDynamicSharedMemorySize, SMEM_BYTES);
    cudaFuncSetAttribute(flow_regression_kernel,
                         cudaFuncAttributePreferredSharedMemoryCarveout, 100);

    flow_regression_kernel<<<NBLOCKS, NT, SMEM_BYTES>>>(x, out);
}

// round 7
// speedup vs baseline: 1.2034x; 1.0636x over previous
#include <cuda_runtime.h>
#include <math_constants.h>
#include <cstdint>

// B=8, U=V=13 (UV=169), H=128, W=160 (HW=20480), TRUNC=4, disp -6..6
#define UV 169
#define VD 13
#define HW 20480
#define NB 8
#define NT 128
#define HW2 (HW / 2)                 // float2 units per plane row
#define TOTAL_PAIRS (NB * HW / 2)    // 81920
#define NBLOCKS (TOTAL_PAIRS / NT)   // 640
#define L2E 1.4426950408889634f
#define NEGBIG (-1e30f)

__device__ __forceinline__ float ex2(float t) {
    float r;
    asm("ex2.approx.f32 %0, %1;" : "=f"(r) : "f"(t));
    return r;
}

__global__ __launch_bounds__(NT)
void flow_regression_kernel(const float* __restrict__ x, float* __restrict__ out) {
    const int g   = blockIdx.x * NT + threadIdx.x;   // pixel-pair id
    const int b   = g / HW2;
    const int rem = g - b * HW2;
    const int pix = rem * 2;

    const float2* xb = (const float2*)(x + (size_t)b * (UV * HW)) + rem;

    // ---- Scan 1: running max + argmax over 169 planes (ascending k, strict >) ----
    float m0 = -CUDART_INF_F, m1 = -CUDART_INF_F;
    int   am0 = 0, am1 = 0;
    {
        const float2* gp = xb;
        #pragma unroll 1
        for (int i = 0; i < VD; i++) {
            const int kb = i * VD;
            #pragma unroll
            for (int j = 0; j < VD; j++) {
                float2 v = gp[j * HW2];
                int k = kb + j;
                if (v.x > m0) { m0 = v.x; am0 = k; }
                if (v.y > m1) { m1 = v.y; am1 = k; }
            }
            gp += VD * HW2;
        }
    }

    const int ui0 = am0 / VD, vi0 = am0 - ui0 * VD;
    const int ui1 = am1 / VD, vi1 = am1 - ui1 * VD;
    const int uLo0 = ui0 - 4, uHi0 = ui0 + 4, vLo0 = vi0 - 4, vHi0 = vi0 + 4;
    const int uLo1 = ui1 - 4, uHi1 = ui1 + 4, vLo1 = vi1 - 4, vHi1 = vi1 + 4;
    const float c0 = m0 * L2E;     // exp(x-m) = ex2(x*L2E - m*L2E)
    const float c1 = m1 * L2E;

    // ---- Scan 2: predicated window softmax over the same 169 planes (L2 hits) ----
    float Z0 = 0.f, sU0 = 0.f, sV0 = 0.f;
    float Z1 = 0.f, sU1 = 0.f, sV1 = 0.f;
    {
        const float2* gp = xb;
        float wu = -6.0f;
        #pragma unroll 1
        for (int u = 0; u < VD; u++) {
            const bool r0 = (u >= uLo0) & (u <= uHi0);
            const bool r1 = (u >= uLo1) & (u <= uHi1);
            #pragma unroll
            for (int j = 0; j < VD; j++) {
                float2 v = gp[j * HW2];
                const bool in0 = r0 & (j >= vLo0) & (j <= vHi0);
                const bool in1 = r1 & (j >= vLo1) & (j <= vHi1);
                const float wv = (float)(j - 6);

                float t0 = fmaf(in0 ? v.x : NEGBIG, L2E, -c0);
                float e0 = ex2(t0);                     // masked -> ex2(-huge) = 0
                Z0  += e0;
                sU0  = fmaf(e0, wu, sU0);
                sV0  = fmaf(e0, wv, sV0);

                float t1 = fmaf(in1 ? v.y : NEGBIG, L2E, -c1);
                float e1 = ex2(t1);
                Z1  += e1;
                sU1  = fmaf(e1, wu, sU1);
                sV1  = fmaf(e1, wv, sV1);
            }
            gp += VD * HW2;
            wu += 1.0f;
        }
    }

    const float i0 = __frcp_rn(Z0);
    const float i1 = __frcp_rn(Z1);
    float2 fu, fv;
    fu.x = sU0 * i0; fu.y = sU1 * i1;
    fv.x = sV0 * i0; fv.y = sV1 * i1;
    *(float2*)(out + ((size_t)b * 2 + 0) * HW + pix) = fu;
    *(float2*)(out + ((size_t)b * 2 + 1) * HW + pix) = fv;
}

extern "C" void kernel_launch(void* const* d_in, const int* in_sizes, int n_in,
                              void* d_out, int out_size) {
    (void)in_sizes; (void)n_in; (void)out_size;
    const float* x = (const float*)d_in[0];
    float* out = (float*)d_out;
    flow_regression_kernel<<<NBLOCKS, NT>>>(x, out);
}

// round 8
// speedup vs baseline: 1.8215x; 1.5135x over previous
#include <cuda_runtime.h>
#include <math_constants.h>
#include <cstdint>

// B=8, U=V=13 (UV=169), H=128, W=160 (HW=20480), TRUNC=4, disp -6..6
#define UV 169
#define VD 13
#define HW 20480
#define PIX 32                    // pixels per chunk
#define NT 128                    // 4 threads per pixel in compute
#define RS 40                     // smem row stride (floats); RS%32==8 -> pass A conflict-free
#define BUF (UV * RS)             // 6760 floats per buffer
#define SMEM_BYTES (2 * BUF * 4)  // 54080 B -> 4 CTAs/SM
#define CH 8                      // chunks per CTA
#define CHUNKS_PER_B (HW / PIX)   // 640
#define NBLOCKS (8 * CHUNKS_PER_B / CH)   // 640
#define L2E 1.4426950408889634f
#define NEGBIG (-1e30f)

__device__ __forceinline__ void cp_async16(unsigned int dst, const float* src) {
    asm volatile("cp.async.cg.shared.global [%0], [%1], 16;" :: "r"(dst), "l"(src) : "memory");
}
__device__ __forceinline__ void cp_commit() {
    asm volatile("cp.async.commit_group;" ::: "memory");
}
template<int N>
__device__ __forceinline__ void cp_wait() {
    asm volatile("cp.async.wait_group %0;" :: "n"(N) : "memory");
}
__device__ __forceinline__ float ex2f(float t) {
    float r;
    asm("ex2.approx.f32 %0, %1;" : "=f"(r) : "f"(t));
    return r;
}

__global__ __launch_bounds__(NT)
void flow_regression_kernel(const float* __restrict__ x, float* __restrict__ out) {
    extern __shared__ float s[];      // 2 buffers of s[uv][RS]
    const int tid = threadIdx.x;
    const int bid = blockIdx.x;
    const unsigned int sbase = (unsigned int)__cvta_generic_to_shared(s);
    const int base_chunk = bid * CH;

    const int sub = tid & 3;          // quarter of per-pixel work
    const int p   = tid >> 2;         // pixel 0..31

    // ---- issue loads for one chunk into buffer nb (16B cp.async, no transpose) ----
    auto issue_load = [&](int g, int nb) {
        int b  = g / CHUNKS_PER_B;
        int ch = g - b * CHUNKS_PER_B;
        const float* base = x + (size_t)b * (UV * HW) + ch * PIX;
        #pragma unroll 4
        for (int i = tid; i < UV * 8; i += NT) {      // 1352 16B lines
            int plane = i >> 3;
            int q     = i & 7;
            cp_async16(sbase + (unsigned int)(nb * BUF + plane * RS + q * 4) * 4u,
                       base + plane * HW + q * 4);
        }
        cp_commit();
    };

    issue_load(base_chunk, 0);        // prologue

    for (int c = 0; c < CH; c++) {
        const int nb = c & 1;
        if (c + 1 < CH) { issue_load(base_chunk + c + 1, nb ^ 1); cp_wait<1>(); }
        else            { cp_wait<0>(); }
        __syncthreads();              // buffer nb loaded & visible to all warps

        const float* sp = s + nb * BUF + p;

        // ---- Pass A: argmax over 169 (ascending uv per lane; ties -> lowest uv) ----
        float m  = -CUDART_INF_F;
        int   am = 0;
        {
            #pragma unroll 6
            for (int t = 0; t < 42; t++) {
                int uv = sub + 4 * t;
                float v = sp[uv * RS];
                if (v > m) { m = v; am = uv; }
            }
            if (sub == 0) {                        // uv = 168
                float v = sp[168 * RS];
                if (v > m) { m = v; am = 168; }
            }
        }
        #pragma unroll
        for (int off = 1; off <= 2; off <<= 1) {
            float mo = __shfl_xor_sync(0xffffffffu, m,  off);
            int   ao = __shfl_xor_sync(0xffffffffu, am, off);
            if (mo > m || (mo == m && ao < am)) { m = mo; am = ao; }
        }
        const int ui = am / VD;
        const int vi = am - ui * VD;
        const float cc = m * L2E;                  // exp(x-m) = ex2(x*L2E - cc)

        // ---- Pass B: 9x9 window, predicated (no pads). Each lane: dv = sub-4, sub, and (+4 for sub0) ----
        float Z = 0.0f, sU = 0.0f, sV = 0.0f;
        {
            const int v0 = vi - 4 + sub;           // j=0
            const int v1 = v0 + 4;                 // j=1
            const int ve = vi + 4;                 // extra, sub==0 only
            const bool okv0 = (unsigned)v0 <= 12u;
            const bool okv1 = (unsigned)v1 <= 12u;
            const bool okve = (sub == 0);          // ve = vi+4: validity folded with u below
            const int vc0 = min(max(v0, 0), 12);
            const int vc1 = min(max(v1, 0), 12);
            const int vce = min(ve, 12);
            const float wv0 = (float)(v0 - 6);
            const float wv1 = (float)(v1 - 6);
            const float wve = (float)(ve - 6);
            const bool okve2 = okve && ((unsigned)ve <= 12u);

            #pragma unroll
            for (int du = 0; du < 9; du++) {
                const int u = ui - 4 + du;
                const bool oku = (unsigned)u <= 12u;
                const int uc = min(max(u, 0), 12);
                const float* r = sp + uc * (VD * RS);
                const float wu = (float)(u - 6);

                float a0 = (oku & okv0) ? r[vc0 * RS] : NEGBIG;
                float e0 = ex2f(fmaf(a0, L2E, -cc));
                Z += e0; sU = fmaf(e0, wu, sU); sV = fmaf(e0, wv0, sV);

                float a1 = (oku & okv1) ? r[vc1 * RS] : NEGBIG;
                float e1 = ex2f(fmaf(a1, L2E, -cc));
                Z += e1; sU = fmaf(e1, wu, sU); sV = fmaf(e1, wv1, sV);

                float ae = (oku & okve2) ? r[vce * RS] : NEGBIG;
                float ee = ex2f(fmaf(ae, L2E, -cc));
                Z += ee; sU = fmaf(ee, wu, sU); sV = fmaf(ee, wve, sV);
            }
        }
        #pragma unroll
        for (int off = 1; off <= 2; off <<= 1) {
            Z  += __shfl_xor_sync(0xffffffffu, Z,  off);
            sU += __shfl_xor_sync(0xffffffffu, sU, off);
            sV += __shfl_xor_sync(0xffffffffu, sV, off);
        }

        if (sub == 0) {
            const int g  = base_chunk + c;
            const int b  = g / CHUNKS_PER_B;
            const int ch = g - b * CHUNKS_PER_B;
            const float inv = __frcp_rn(Z);
            const int pix = ch * PIX + p;
            out[(b * 2 + 0) * HW + pix] = sU * inv;
            out[(b * 2 + 1) * HW + pix] = sV * inv;
        }
        __syncthreads();              // reads of buffer nb done before it is refilled
    }
}

extern "C" void kernel_launch(void* const* d_in, const int* in_sizes, int n_in,
                              void* d_out, int out_size) {
    (void)in_sizes; (void)n_in; (void)out_size;
    const float* x = (const float*)d_in[0];
    float* out = (float*)d_out;

    cudaFuncSetAttribute(flow_regression_kernel,
                         cudaFuncAttributeMaxDynamicSharedMemorySize, SMEM_BYTES);
    cudaFuncSetAttribute(flow_regression_kernel,
                         cudaFuncAttributePreferredSharedMemoryCarveout, 100);

    flow_regression_kernel<<<NBLOCKS, NT, SMEM_BYTES>>>(x, out);
}

// round 9
// speedup vs baseline: 1.8626x; 1.0226x over previous
#include <cuda_runtime.h>
#include <math_constants.h>
#include <cstdint>

// B=8, U=V=13 (UV=169), H=128, W=160 (HW=20480), TRUNC=4, disp -6..6
#define UV 169
#define VD 13
#define HW 20480
#define PIX 32                    // pixels per chunk
#define NT 256                    // 8 threads per pixel in compute
#define RS 40                     // smem row stride (floats)
#define BUF (UV * RS)             // 6760 floats per buffer
#define SMEM_BYTES (2 * BUF * 4)  // 54080 B -> 4 CTAs/SM (211KB of 228KB)
#define CH 8                      // chunks per CTA
#define CHUNKS_PER_B (HW / PIX)   // 640
#define NBLOCKS (8 * CHUNKS_PER_B / CH)   // 640
#define L2E 1.4426950408889634f
#define NEGBIG (-1e30f)

__device__ __forceinline__ void cp_async16(unsigned int dst, const float* src) {
    asm volatile("cp.async.cg.shared.global [%0], [%1], 16;" :: "r"(dst), "l"(src) : "memory");
}
__device__ __forceinline__ void cp_commit() {
    asm volatile("cp.async.commit_group;" ::: "memory");
}
template<int N>
__device__ __forceinline__ void cp_wait() {
    asm volatile("cp.async.wait_group %0;" :: "n"(N) : "memory");
}
__device__ __forceinline__ float ex2f(float t) {
    float r;
    asm("ex2.approx.f32 %0, %1;" : "=f"(r) : "f"(t));
    return r;
}

__global__ __launch_bounds__(NT)
void flow_regression_kernel(const float* __restrict__ x, float* __restrict__ out) {
    extern __shared__ float s[];      // 2 buffers of s[uv][RS]
    const int tid = threadIdx.x;
    const int bid = blockIdx.x;
    const unsigned int sbase = (unsigned int)__cvta_generic_to_shared(s);
    const int base_chunk = bid * CH;

    const int sub = tid & 7;          // eighth of per-pixel work
    const int p   = tid >> 3;         // pixel 0..31

    // ---- issue loads for one chunk into buffer nb (16B cp.async, no transpose) ----
    auto issue_load = [&](int g, int nb) {
        int b  = g / CHUNKS_PER_B;
        int ch = g - b * CHUNKS_PER_B;
        const float* base = x + (size_t)b * (UV * HW) + ch * PIX;
        #pragma unroll 3
        for (int i = tid; i < UV * 8; i += NT) {      // 1352 16B lines
            int plane = i >> 3;
            int q     = i & 7;
            cp_async16(sbase + (unsigned int)(nb * BUF + plane * RS + q * 4) * 4u,
                       base + plane * HW + q * 4);
        }
        cp_commit();
    };

    issue_load(base_chunk, 0);        // prologue

    for (int c = 0; c < CH; c++) {
        const int nb = c & 1;
        if (c + 1 < CH) { issue_load(base_chunk + c + 1, nb ^ 1); cp_wait<1>(); }
        else            { cp_wait<0>(); }
        __syncthreads();              // buffer nb loaded & visible to all warps

        const float* sp = s + nb * BUF + p;

        // ---- Pass A: argmax over 169, 8-way split (ascending uv; ties -> lowest uv) ----
        float m  = -CUDART_INF_F;
        int   am = 0;
        {
            #pragma unroll 7
            for (int t = 0; t < 21; t++) {
                int uv = sub + 8 * t;
                float v = sp[uv * RS];
                if (v > m) { m = v; am = uv; }
            }
            if (sub == 0) {                        // uv = 168
                float v = sp[168 * RS];
                if (v > m) { m = v; am = 168; }
            }
        }
        #pragma unroll
        for (int off = 1; off <= 4; off <<= 1) {
            float mo = __shfl_xor_sync(0xffffffffu, m,  off);
            int   ao = __shfl_xor_sync(0xffffffffu, am, off);
            if (mo > m || (mo == m && ao < am)) { m = mo; am = ao; }
        }
        const int ui = am / VD;
        const int vi = am - ui * VD;
        const float cc = m * L2E;                  // exp(x-m) = ex2(x*L2E - cc)

        // ---- Pass B: 9x9 window (81 elements), exactly 11 slots per thread ----
        // base: (du=0..8, dv=sub); extraA: (du=sub, dv=8); extraB: (du=8, dv=8) on sub0
        float Z = 0.0f, sU = 0.0f, sV = 0.0f;
        {
            const int v0 = vi - 4 + sub;
            const bool okv0 = (unsigned)v0 <= 12u;
            const int vc0 = min(max(v0, 0), 12);
            const float wv0 = (float)(v0 - 6);

            #pragma unroll
            for (int du = 0; du < 9; du++) {
                const int u = ui - 4 + du;
                const bool oku = (unsigned)u <= 12u;
                const int uc = min(max(u, 0), 12);
                const float wu = (float)(u - 6);
                float a = (oku & okv0) ? sp[(uc * VD + vc0) * RS] : NEGBIG;
                float e = ex2f(fmaf(a, L2E, -cc));
                Z += e; sU = fmaf(e, wu, sU); sV = fmaf(e, wv0, sV);
            }
            {   // extra A: du = sub (covers dv=8 for du rows 0..7)
                const int u  = ui - 4 + sub;
                const int ve = vi + 4;
                const bool ok = ((unsigned)u <= 12u) & ((unsigned)ve <= 12u);
                const int uc  = min(max(u, 0), 12);
                const int vce = min(ve, 12);
                float a = ok ? sp[(uc * VD + vce) * RS] : NEGBIG;
                float e = ex2f(fmaf(a, L2E, -cc));
                Z += e; sU = fmaf(e, (float)(u - 6), sU); sV = fmaf(e, (float)(ve - 6), sV);
            }
            {   // extra B: (du=8, dv=8), sub 0 only
                const int u  = ui + 4;
                const int ve = vi + 4;
                const bool ok = (sub == 0) & ((unsigned)u <= 12u) & ((unsigned)ve <= 12u);
                const int uc  = min(u, 12);
                const int vce = min(ve, 12);
                float a = ok ? sp[(uc * VD + vce) * RS] : NEGBIG;
                float e = ex2f(fmaf(a, L2E, -cc));
                Z += e; sU = fmaf(e, (float)(u - 6), sU); sV = fmaf(e, (float)(ve - 6), sV);
            }
        }
        #pragma unroll
        for (int off = 1; off <= 4; off <<= 1) {
            Z  += __shfl_xor_sync(0xffffffffu, Z,  off);
            sU += __shfl_xor_sync(0xffffffffu, sU, off);
            sV += __shfl_xor_sync(0xffffffffu, sV, off);
        }

        if (sub == 0) {
            const int g  = base_chunk + c;
            const int b  = g / CHUNKS_PER_B;
            const int ch = g - b * CHUNKS_PER_B;
            const float inv = __frcp_rn(Z);
            const int pix = ch * PIX + p;
            out[(b * 2 + 0) * HW + pix] = sU * inv;
            out[(b * 2 + 1) * HW + pix] = sV * inv;
        }
        __syncthreads();              // reads of buffer nb done before it is refilled
    }
}

extern "C" void kernel_launch(void* const* d_in, const int* in_sizes, int n_in,
                              void* d_out, int out_size) {
    (void)in_sizes; (void)n_in; (void)out_size;
    const float* x = (const float*)d_in[0];
    float* out = (float*)d_out;

    cudaFuncSetAttribute(flow_regression_kernel,
                         cudaFuncAttributeMaxDynamicSharedMemorySize, SMEM_BYTES);
    cudaFuncSetAttribute(flow_regression_kernel,
                         cudaFuncAttributePreferredSharedMemoryCarveout, 100);

    flow_regression_kernel<<<NBLOCKS, NT, SMEM_BYTES>>>(x, out);
}

// round 10
// speedup vs baseline: 2.0994x; 1.1272x over previous
#include <cuda_runtime.h>
#include <math_constants.h>
#include <cstdint>

// B=8, U=V=13 (UV=169), H=128, W=160 (HW=20480), TRUNC=4, disp -6..6
#define UV 169
#define VD 13
#define HW 20480
#define PIX 32                    // pixels per chunk
#define NT 256                    // 8 threads per pixel in compute
#define RS 36                     // smem row stride; (4*sub+p')%32 bijective -> conflict-free
#define BUF (UV * RS)             // 6084 floats per buffer
#define SMEM_BYTES (2 * BUF * 4)  // 48672 B -> 4 CTAs/SM
#define CHUNKS_PER_B (HW / PIX)   // 640
#define NCHUNKS (8 * CHUNKS_PER_B)  // 5120
#define L2E 1.4426950408889634f
#define NEGBIG (-1e30f)

__device__ __forceinline__ void cp_async16(unsigned int dst, const float* src) {
    asm volatile("cp.async.cg.shared.global [%0], [%1], 16;" :: "r"(dst), "l"(src) : "memory");
}
__device__ __forceinline__ void cp_commit() {
    asm volatile("cp.async.commit_group;" ::: "memory");
}
template<int N>
__device__ __forceinline__ void cp_wait() {
    asm volatile("cp.async.wait_group %0;" :: "n"(N) : "memory");
}
__device__ __forceinline__ float ex2f(float t) {
    float r;
    asm("ex2.approx.f32 %0, %1;" : "=f"(r) : "f"(t));
    return r;
}

__global__ __launch_bounds__(NT)
void flow_regression_kernel(const float* __restrict__ x, float* __restrict__ out) {
    extern __shared__ float s[];      // 2 buffers of s[uv][RS]
    const int tid = threadIdx.x;
    const int bid = blockIdx.x;
    const int G   = gridDim.x;        // persistent CTAs; chunks grid-strided
    const unsigned int sbase = (unsigned int)__cvta_generic_to_shared(s);

    const int sub = tid & 7;          // eighth of per-pixel work
    const int p   = tid >> 3;         // pixel 0..31

    // ---- issue loads for one chunk into buffer nb (16B cp.async, no transpose) ----
    auto issue_load = [&](int g, int nb) {
        int b  = g / CHUNKS_PER_B;
        int ch = g - b * CHUNKS_PER_B;
        const float* base = x + (size_t)b * (UV * HW) + ch * PIX;
        #pragma unroll 3
        for (int i = tid; i < UV * 8; i += NT) {      // 1352 16B lines
            int plane = i >> 3;
            int q     = i & 7;
            cp_async16(sbase + (unsigned int)(nb * BUF + plane * RS + q * 4) * 4u,
                       base + plane * HW + q * 4);
        }
        cp_commit();
    };

    issue_load(bid, 0);               // prologue: first chunk -> buf 0
    int nb = 0;

    for (int g = bid; g < NCHUNKS; g += G) {
        cp_wait<0>();                 // this thread's copies for chunk g done
        __syncthreads();              // all threads' copies visible; all reads of nb^1 finished
        if (g + G < NCHUNKS) issue_load(g + G, nb ^ 1);   // overlaps with compute below

        const float* sp = s + nb * BUF + p;

        // ---- Pass A: argmax over 169, 8-way split (ascending uv; ties -> lowest uv) ----
        float m  = -CUDART_INF_F;
        int   am = 0;
        {
            #pragma unroll 7
            for (int t = 0; t < 21; t++) {
                int uv = sub + 8 * t;
                float v = sp[uv * RS];
                if (v > m) { m = v; am = uv; }
            }
            if (sub == 0) {                        // uv = 168
                float v = sp[168 * RS];
                if (v > m) { m = v; am = 168; }
            }
        }
        #pragma unroll
        for (int off = 1; off <= 4; off <<= 1) {
            float mo = __shfl_xor_sync(0xffffffffu, m,  off);
            int   ao = __shfl_xor_sync(0xffffffffu, am, off);
            if (mo > m || (mo == m && ao < am)) { m = mo; am = ao; }
        }
        const int ui = am / VD;
        const int vi = am - ui * VD;
        const float cc = m * L2E;                  // exp(x-m) = ex2(x*L2E - cc)

        // ---- Pass B: 9x9 window (81 elements), ~11 slots per thread ----
        float Z = 0.0f, sU = 0.0f, sV = 0.0f;
        {
            const int v0 = vi - 4 + sub;
            const bool okv0 = (unsigned)v0 <= 12u;
            const int vc0 = min(max(v0, 0), 12);
            const float wv0 = (float)(v0 - 6);

            #pragma unroll
            for (int du = 0; du < 9; du++) {
                const int u = ui - 4 + du;
                const bool oku = (unsigned)u <= 12u;
                const int uc = min(max(u, 0), 12);
                const float wu = (float)(u - 6);
                float a = (oku & okv0) ? sp[(uc * VD + vc0) * RS] : NEGBIG;
                float e = ex2f(fmaf(a, L2E, -cc));
                Z += e; sU = fmaf(e, wu, sU); sV = fmaf(e, wv0, sV);
            }
            {   // extra A: du = sub (covers dv=8 for du rows 0..7)
                const int u  = ui - 4 + sub;
                const int ve = vi + 4;
                const bool ok = ((unsigned)u <= 12u) & ((unsigned)ve <= 12u);
                const int uc  = min(max(u, 0), 12);
                const int vce = min(ve, 12);
                float a = ok ? sp[(uc * VD + vce) * RS] : NEGBIG;
                float e = ex2f(fmaf(a, L2E, -cc));
                Z += e; sU = fmaf(e, (float)(u - 6), sU); sV = fmaf(e, (float)(ve - 6), sV);
            }
            {   // extra B: (du=8, dv=8), sub 0 only
                const int u  = ui + 4;
                const int ve = vi + 4;
                const bool ok = (sub == 0) & ((unsigned)u <= 12u) & ((unsigned)ve <= 12u);
                const int uc  = min(u, 12);
                const int vce = min(ve, 12);
                float a = ok ? sp[(uc * VD + vce) * RS] : NEGBIG;
                float e = ex2f(fmaf(a, L2E, -cc));
                Z += e; sU = fmaf(e, (float)(u - 6), sU); sV = fmaf(e, (float)(ve - 6), sV);
            }
        }
        #pragma unroll
        for (int off = 1; off <= 4; off <<= 1) {
            Z  += __shfl_xor_sync(0xffffffffu, Z,  off);
            sU += __shfl_xor_sync(0xffffffffu, sU, off);
            sV += __shfl_xor_sync(0xffffffffu, sV, off);
        }

        if (sub == 0) {
            const int b  = g / CHUNKS_PER_B;
            const int ch = g - b * CHUNKS_PER_B;
            const float inv = __frcp_rn(Z);
            const int pix = ch * PIX + p;
            out[(b * 2 + 0) * HW + pix] = sU * inv;
            out[(b * 2 + 1) * HW + pix] = sV * inv;
        }
        nb ^= 1;
        // no trailing barrier: next iteration's __syncthreads (after cp_wait)
        // orders these reads before the refill of this buffer.
    }
}

extern "C" void kernel_launch(void* const* d_in, const int* in_sizes, int n_in,
                              void* d_out, int out_size) {
    (void)in_sizes; (void)n_in; (void)out_size;
    const float* x = (const float*)d_in[0];
    float* out = (float*)d_out;

    static int nsm = 0;
    if (nsm == 0) {
        cudaDeviceGetAttribute(&nsm, cudaDevAttrMultiProcessorCount, 0);
        if (nsm <= 0) nsm = 148;
        cudaFuncSetAttribute(flow_regression_kernel,
                             cudaFuncAttributeMaxDynamicSharedMemorySize, SMEM_BYTES);
        cudaFuncSetAttribute(flow_regression_kernel,
                             cudaFuncAttributePreferredSharedMemoryCarveout, 100);
    }

    const int nblocks = 4 * nsm;      // persistent: 4 CTAs per SM
    flow_regression_kernel<<<nblocks, NT, SMEM_BYTES>>>(x, out);
}

// round 11
// speedup vs baseline: 2.1415x; 1.0200x over previous
#include <cuda_runtime.h>
#include <math_constants.h>
#include <cstdint>

// B=8, U=V=13 (UV=169), H=128, W=160 (HW=20480), TRUNC=4, disp -6..6
#define UV 169
#define VD 13
#define HW 20480
#define PIX 32                    // pixels per chunk
#define NT 256                    // 8 threads per pixel
#define RS 36                     // smem row stride; pass A bank (4*sub+p) bijective
#define BUF (UV * RS)             // 6084 floats per buffer
#define GUARD 144                 // guard floats each side (covers rows [-4, +4] overhang)
#define SMEM_FLOATS (2 * GUARD + 2 * BUF)       // 12456
#define SMEM_BYTES (SMEM_FLOATS * 4)            // 49824 B -> 4 CTAs/SM
#define CHUNKS_PER_B (HW / PIX)   // 640
#define NCHUNKS (8 * CHUNKS_PER_B)  // 5120
#define L2E 1.4426950408889634f
#define NEGBIG (-1e30f)

__device__ __forceinline__ void cp_async16(unsigned int dst, const float* src) {
    asm volatile("cp.async.cg.shared.global [%0], [%1], 16;" :: "r"(dst), "l"(src) : "memory");
}
__device__ __forceinline__ void cp_commit() {
    asm volatile("cp.async.commit_group;" ::: "memory");
}
template<int N>
__device__ __forceinline__ void cp_wait() {
    asm volatile("cp.async.wait_group %0;" :: "n"(N) : "memory");
}
__device__ __forceinline__ float ex2f(float t) {
    float r;
    asm("ex2.approx.f32 %0, %1;" : "=f"(r) : "f"(t));
    return r;
}

__global__ __launch_bounds__(NT)
void flow_regression_kernel(const float* __restrict__ x, float* __restrict__ out) {
    extern __shared__ float s_raw[];
    float* s0 = s_raw + GUARD;        // buffer 0 base; buffer nb at s0 + nb*BUF
    const int tid = threadIdx.x;
    const int bid = blockIdx.x;
    const int G   = gridDim.x;
    const unsigned int sbase0 = (unsigned int)__cvta_generic_to_shared(s0);

    const int sub = tid & 7;          // eighth of per-pixel work
    const int p   = tid >> 3;         // pixel 0..31

    const int plane0 = tid >> 3;      // line tid: plane index
    const int q0     = (tid & 7) * 4; // float offset within 32-pixel chunk

    // ---- issue loads for one chunk: 1352 16B lines, incremental addressing ----
    auto issue_load = [&](int g, int nb) {
        int b  = g / CHUNKS_PER_B;
        int ch = g - b * CHUNKS_PER_B;
        const float* gp = x + (size_t)b * (UV * HW) + ch * PIX + plane0 * HW + q0;
        unsigned int dst = sbase0 + (unsigned int)(nb * BUF + plane0 * RS + q0) * 4u;
        #pragma unroll
        for (int k = 0; k < 5; k++) {                 // lines tid + 256k, k<5 (1280)
            cp_async16(dst, gp);
            gp  += 32 * HW;
            dst += 32 * RS * 4;
        }
        if (tid < 72) cp_async16(dst, gp);            // lines 1280..1351
        cp_commit();
    };

    issue_load(bid, 0);
    int nb = 0;

    for (int g = bid; g < NCHUNKS; g += G) {
        cp_wait<0>();
        __syncthreads();              // buffer nb visible; reads of nb^1 all finished
        if (g + G < NCHUNKS) issue_load(g + G, nb ^ 1);   // overlaps compute below

        const float* sp = s0 + nb * BUF + p;

        // ---- Pass A: argmax over 169, 8-way split (ascending uv; ties -> lowest uv) ----
        float m  = -CUDART_INF_F;
        int   am = 0;
        {
            const float* r = sp + sub * RS;
            #pragma unroll 7
            for (int t = 0; t < 21; t++) {
                float v = r[t * 8 * RS];
                int uv = sub + 8 * t;
                if (v > m) { m = v; am = uv; }
            }
            if (sub == 0) {
                float v = sp[168 * RS];
                if (v > m) { m = v; am = 168; }
            }
        }
        #pragma unroll
        for (int off = 1; off <= 4; off <<= 1) {
            float mo = __shfl_xor_sync(0xffffffffu, m,  off);
            int   ao = __shfl_xor_sync(0xffffffffu, am, off);
            if (mo > m || (mo == m && ao < am)) { m = mo; am = ao; }
        }
        const int ui = am / VD;
        const int vi = am - ui * VD;
        const float cc = m * L2E;                  // exp(x-m) = ex2(x*L2E - cc)

        // ---- Pass B (row-based): thread owns row du=sub-4; row du=+4 distributed ----
        // v-only validity mask over j=0..8 (v = vi-4+j valid iff 0<=v<=12)
        unsigned int vmV = 0x1FFu;
        if (vi < 4) vmV &= (0x1FFu << (4 - vi));
        if (vi > 8) vmV &= (0x1FFu >> (vi - 8));

        const int u   = ui + sub - 4;
        const bool oku = (unsigned)u <= 12u;
        const int uc  = min(max(u, 0), 12);
        const float wu = (float)(u - 6);
        const unsigned int vm = oku ? vmV : 0u;    // folded mask for the base row

        float Zb = 0.0f, Zx = 0.0f, T = 0.0f;      // T = sum e*j
        {
            const float* r = sp + (uc * VD + vi - 4) * RS;   // j=0 base (guards absorb overhang)
            #pragma unroll
            for (int j = 0; j < 9; j++) {
                float a = (vm & (1u << j)) ? r[j * RS] : NEGBIG;
                float e = ex2f(fmaf(a, L2E, -cc));
                Zb += e;
                T = fmaf(e, (float)j, T);
            }
        }
        // extra row du=+4: element j=sub on every thread, j=8 on sub0
        const int u4 = ui + 4;
        const bool ok4 = (u4 <= 12);
        const int uc4 = min(u4, 12);
        const float wu4 = (float)(u4 - 6);
        {
            const float* r4 = sp + (uc4 * VD + vi - 4) * RS;
            bool oke = ok4 && ((vmV >> sub) & 1u);
            float a1 = oke ? r4[sub * RS] : NEGBIG;
            float e1 = ex2f(fmaf(a1, L2E, -cc));
            Zx += e1;
            T = fmaf(e1, (float)sub, T);

            bool oke8 = ok4 && (sub == 0) && ((vmV >> 8) & 1u);
            float a2 = oke8 ? r4[8 * RS] : NEGBIG;
            float e2 = ex2f(fmaf(a2, L2E, -cc));
            Zx += e2;
            T = fmaf(e2, 8.0f, T);
        }

        float Z  = Zb + Zx;
        float sU = fmaf(wu, Zb, wu4 * Zx);
        #pragma unroll
        for (int off = 1; off <= 4; off <<= 1) {
            Z  += __shfl_xor_sync(0xffffffffu, Z,  off);
            sU += __shfl_xor_sync(0xffffffffu, sU, off);
            T  += __shfl_xor_sync(0xffffffffu, T,  off);
        }

        if (sub == 0) {
            const int b  = g / CHUNKS_PER_B;
            const int ch = g - b * CHUNKS_PER_B;
            const float inv = __frcp_rn(Z);
            const float sV = fmaf((float)(vi - 10), Z, T);   // wv = (vi-10)+j
            const int pix = ch * PIX + p;
            out[(b * 2 + 0) * HW + pix] = sU * inv;
            out[(b * 2 + 1) * HW + pix] = sV * inv;
        }
        nb ^= 1;
        // next iteration's __syncthreads orders these reads before refill
    }
}

extern "C" void kernel_launch(void* const* d_in, const int* in_sizes, int n_in,
                              void* d_out, int out_size) {
    (void)in_sizes; (void)n_in; (void)out_size;
    const float* x = (const float*)d_in[0];
    float* out = (float*)d_out;

    static int nsm = 0;
    if (nsm == 0) {
        cudaDeviceGetAttribute(&nsm, cudaDevAttrMultiProcessorCount, 0);
        if (nsm <= 0) nsm = 148;
        cudaFuncSetAttribute(flow_regression_kernel,
                             cudaFuncAttributeMaxDynamicSharedMemorySize, SMEM_BYTES);
        cudaFuncSetAttribute(flow_regression_kernel,
                             cudaFuncAttributePreferredSharedMemoryCarveout, 100);
    }

    const int nblocks = 4 * nsm;      // persistent: 4 CTAs per SM
    flow_regression_kernel<<<nblocks, NT, SMEM_BYTES>>>(x, out);
}